// round 2
// baseline (speedup 1.0000x reference)
#include <cuda_runtime.h>
#include <cooperative_groups.h>
#include <math.h>

namespace cg = cooperative_groups;

#define BATCH  256
#define D      512
#define S      196
#define HALF_D 256

// scratch: w[b,d] = memory[b,d]*v[b,d] + ctrl[b,d]*w_attn[d],  v = (ctrl*w_attn) @ W
__device__ float g_w[BATCH * D];

// ---------------------------------------------------------------------------
// Kernel 1 (prep): tiny fp32 GEMM with 4-way k-split for occupancy.
// Grid (4 d-tiles, 32 b-tiles), 512 threads. CTA tile: 8 batches x 128 d.
// Threads: dl = tid&127 (d within tile), ez = tid>>7 (k-quarter, 128 e each).
// ---------------------------------------------------------------------------
__global__ __launch_bounds__(512) void prep_kernel(
    const float* __restrict__ memory,
    const float* __restrict__ ctrl,
    const float* __restrict__ W,       // [e, d] row-major
    const float* __restrict__ w_attn)
{
    __shared__ float u_s[8 * 512];     // [j][e] = ctrl[b0+j,e]*w_attn[e]; reused for reduction

    const int tid = threadIdx.x;
    const int dl  = tid & 127;
    const int ez  = tid >> 7;          // 0..3
    const int d   = blockIdx.x * 128 + dl;
    const int b0  = blockIdx.y * 8;

    for (int idx = tid; idx < 8 * 512; idx += 512) {
        int j = idx >> 9, e = idx & 511;
        u_s[idx] = ctrl[(b0 + j) * D + e] * w_attn[e];
    }
    __syncthreads();

    float acc[8];
#pragma unroll
    for (int j = 0; j < 8; j++) acc[j] = 0.f;

    const int e0 = ez * 128;
#pragma unroll 4
    for (int e = e0; e < e0 + 128; e += 4) {
        float w0 = W[(e + 0) * D + d];
        float w1 = W[(e + 1) * D + d];
        float w2 = W[(e + 2) * D + d];
        float w3 = W[(e + 3) * D + d];
#pragma unroll
        for (int j = 0; j < 8; j++) {
            float4 u4 = *reinterpret_cast<const float4*>(&u_s[j * 512 + e]);
            acc[j] += w0 * u4.x + w1 * u4.y + w2 * u4.z + w3 * u4.w;
        }
    }
    __syncthreads();

    // reduce 4 k-quarters: reuse u_s as part[ez][j][dl]
#pragma unroll
    for (int j = 0; j < 8; j++)
        u_s[(ez * 8 + j) * 128 + dl] = acc[j];
    __syncthreads();

    for (int o = tid; o < 1024; o += 512) {
        int j = o >> 7, dd = o & 127;
        float v = u_s[j * 128 + dd] + u_s[(8 + j) * 128 + dd]
                + u_s[(16 + j) * 128 + dd] + u_s[(24 + j) * 128 + dd];
        int b  = b0 + j;
        int dg = blockIdx.x * 128 + dd;
        g_w[b * D + dg] = memory[b * D + dg] * v + ctrl[b * D + dg] * w_attn[dg];
    }
}

// ---------------------------------------------------------------------------
// Kernel 2: 2-CTA cluster per batch. Each CTA owns HALF_D rows of kb[b],
// stages them in smem during the logit pass, exchanges partial rai via DSMEM,
// softmaxes redundantly, then does the weighted sum entirely from smem.
// kb is read from DRAM exactly once.
// ---------------------------------------------------------------------------
__global__ __launch_bounds__(512) __cluster_dims__(2, 1, 1)
void read_unit_kernel(const float* __restrict__ kb,   // [B, D, S]
                      float* __restrict__ out)        // [B, D]
{
    extern __shared__ float kb_s[];                   // HALF_D * S floats (200,704 B)

    cg::cluster_group cluster = cg::this_cluster();
    const int rank = blockIdx.x & 1;
    const int b    = blockIdx.x >> 1;
    const int tid  = threadIdx.x;
    const int wid  = tid >> 5;
    const int lane = tid & 31;

    __shared__ float w_s[HALF_D];
    __shared__ float part[16][200];   // per-warp partial rai (padded stride)
    __shared__ float rai_mine[200];   // this CTA's partial rai (DSMEM-exchanged)
    __shared__ float rvi_s[200];
    __shared__ float red[16];

    const float* __restrict__ kbb = kb + (size_t)b * (D * S) + (size_t)rank * (HALF_D * S);

    if (tid < HALF_D) w_s[tid] = g_w[b * D + rank * HALF_D + tid];
    __syncthreads();

    // ---- Pass A: stream my kb half: accumulate partial rai AND stage to smem ----
    float acc[7];
#pragma unroll
    for (int c = 0; c < 7; c++) acc[c] = 0.f;

#pragma unroll 2
    for (int dl = wid; dl < HALF_D; dl += 16) {
        const float wv = w_s[dl];
        const float* __restrict__ row = kbb + dl * S;
        float* __restrict__ srow = kb_s + dl * S;
#pragma unroll
        for (int c = 0; c < 6; c++) {
            float v = row[c * 32 + lane];
            acc[c] += wv * v;
            srow[c * 32 + lane] = v;
        }
        if (lane < 4) {
            float v = row[192 + lane];
            acc[6] += wv * v;
            srow[192 + lane] = v;
        }
    }
#pragma unroll
    for (int c = 0; c < 7; c++) {
        int s = c * 32 + lane;
        if (s < S) part[wid][s] = acc[c];
    }
    __syncthreads();

    // deterministic cross-warp reduction of my partial
    if (tid < S) {
        float sum = 0.f;
#pragma unroll
        for (int k = 0; k < 16; k++) sum += part[k][tid];
        rai_mine[tid] = sum;
    }
    __syncthreads();
    cluster.sync();   // partials visible cluster-wide

    // ---- exchange partials via DSMEM, form full rai ----
    float* peer_rai = cluster.map_shared_rank(rai_mine, rank ^ 1);
    float rai = -INFINITY;
    if (tid < S) rai = rai_mine[tid] + peer_rai[tid];   // fp add commutative -> both CTAs identical
    cluster.sync();   // both CTAs done reading peer smem before anyone proceeds/exits

    // ---- softmax over s (each CTA computes identical full softmax) ----
    float m = rai;
#pragma unroll
    for (int off = 16; off > 0; off >>= 1)
        m = fmaxf(m, __shfl_xor_sync(0xffffffff, m, off));
    if (lane == 0) red[wid] = m;
    __syncthreads();
    if (wid == 0) {
        float v = (lane < 16) ? red[lane] : -INFINITY;
#pragma unroll
        for (int off = 8; off > 0; off >>= 1)
            v = fmaxf(v, __shfl_xor_sync(0xffffffff, v, off));
        if (lane == 0) red[0] = v;
    }
    __syncthreads();
    const float gmax = red[0];
    __syncthreads();

    float p = (tid < S) ? expf(rai - gmax) : 0.f;
    float sacc = p;
#pragma unroll
    for (int off = 16; off > 0; off >>= 1)
        sacc += __shfl_xor_sync(0xffffffff, sacc, off);
    if (lane == 0) red[wid] = sacc;
    __syncthreads();
    if (wid == 0) {
        float v = (lane < 16) ? red[lane] : 0.f;
#pragma unroll
        for (int off = 8; off > 0; off >>= 1)
            v += __shfl_xor_sync(0xffffffff, v, off);
        if (lane == 0) red[0] = v;
    }
    __syncthreads();
    const float inv_sum = 1.f / red[0];
    if (tid < S) rvi_s[tid] = p * inv_sum;
    __syncthreads();

    // ---- Pass B: weighted sum over s, entirely from smem ----
#pragma unroll 2
    for (int el = wid; el < HALF_D; el += 16) {
        const float* __restrict__ srow = kb_s + el * S;
        float sum = 0.f;
#pragma unroll
        for (int c = 0; c < 6; c++)
            sum += srow[c * 32 + lane] * rvi_s[c * 32 + lane];
        if (lane < 4)
            sum += srow[192 + lane] * rvi_s[192 + lane];
#pragma unroll
        for (int off = 16; off > 0; off >>= 1)
            sum += __shfl_xor_sync(0xffffffff, sum, off);
        if (lane == 0) out[b * D + rank * HALF_D + el] = sum;
    }
}

extern "C" void kernel_launch(void* const* d_in, const int* in_sizes, int n_in,
                              void* d_out, int out_size)
{
    const float* memory = (const float*)d_in[0];  // [B, D]
    const float* ctrl   = (const float*)d_in[1];  // [B, D]
    const float* kb     = (const float*)d_in[2];  // [B, D, S]
    const float* W      = (const float*)d_in[3];  // [D, D]
    // d_in[4] = b_concat: constant s-independent shift inside softmax -> drops out
    const float* w_attn = (const float*)d_in[5];  // [D]
    float* out = (float*)d_out;                   // [B, D]

    const int kb_smem = HALF_D * S * sizeof(float);  // 200,704 B
    cudaFuncSetAttribute(read_unit_kernel,
                         cudaFuncAttributeMaxDynamicSharedMemorySize, kb_smem);

    prep_kernel<<<dim3(4, 32), 512>>>(memory, ctrl, W, w_attn);
    read_unit_kernel<<<2 * BATCH, 512, kb_smem>>>(kb, out);
}

// round 3
// speedup vs baseline: 1.7266x; 1.7266x over previous
#include <cuda_runtime.h>
#include <math.h>

#define BATCH  256
#define D      512
#define S      196

// device scratch (no allocs allowed)
__device__ float g_w[BATCH * D];        // w[b,d] = mem*v + ctrl*w_attn
__device__ float g_rai[2 * BATCH * 256]; // per-half partial logits, padded stride 256

// ---------------------------------------------------------------------------
// Prep: w[b,d] = memory[b,d]*(sum_e u[b,e]*W[e,d]) + ctrl[b,d]*w_attn[d],
//       u[b,e] = ctrl[b,e]*w_attn[e].
// Grid (4 d-tiles, 32 b-tiles), 1024 threads: dl=tid&127, ez=tid>>7 (8-way
// k-split, 64 e each). High warp count hides L2 latency on W loads.
// ---------------------------------------------------------------------------
__global__ __launch_bounds__(1024) void prep_kernel(
    const float* __restrict__ memory,
    const float* __restrict__ ctrl,
    const float* __restrict__ W,       // [e, d] row-major
    const float* __restrict__ w_attn)
{
    __shared__ float sm[8192];         // phase1: u_s[e*8+j] (4096); phase2: partials (8192)

    const int tid = threadIdx.x;
    const int dl  = tid & 127;
    const int ez  = tid >> 7;          // 0..7
    const int d   = blockIdx.x * 128 + dl;
    const int b0  = blockIdx.y * 8;

    // u_s[e*8 + j] = ctrl[b0+j, e] * w_attn[e]
    for (int idx = tid; idx < 4096; idx += 1024) {
        int e = idx >> 3, j = idx & 7;
        sm[idx] = ctrl[(b0 + j) * D + e] * w_attn[e];
    }
    __syncthreads();

    float acc[8];
#pragma unroll
    for (int j = 0; j < 8; j++) acc[j] = 0.f;

    const int e0 = ez * 64;
#pragma unroll 8
    for (int e = e0; e < e0 + 64; e++) {
        float wv = W[e * D + d];
        float4 ua = *reinterpret_cast<const float4*>(&sm[e * 8]);
        float4 ub = *reinterpret_cast<const float4*>(&sm[e * 8 + 4]);
        acc[0] += wv * ua.x;  acc[1] += wv * ua.y;
        acc[2] += wv * ua.z;  acc[3] += wv * ua.w;
        acc[4] += wv * ub.x;  acc[5] += wv * ub.y;
        acc[6] += wv * ub.z;  acc[7] += wv * ub.w;
    }
    __syncthreads();

    // partials: sm[ez*1024 + j*128 + dl]
#pragma unroll
    for (int j = 0; j < 8; j++)
        sm[ez * 1024 + j * 128 + dl] = acc[j];
    __syncthreads();

    {
        int j  = tid >> 7;             // 0..7
        int dd = tid & 127;
        float v = 0.f;
#pragma unroll
        for (int k = 0; k < 8; k++) v += sm[k * 1024 + j * 128 + dd];
        int b  = b0 + j;
        int dg = blockIdx.x * 128 + dd;
        g_w[b * D + dg] = memory[b * D + dg] * v + ctrl[b * D + dg] * w_attn[dg];
    }
}

// ---------------------------------------------------------------------------
// Kernel A: partial logits. Grid 512 = (b, half): each CTA owns 256 d-rows.
// 256 threads / 8 warps; warp-per-row, float4 loads (row = 49 float4, 16B
// aligned since 196*4=784=49*16). Streams kb from DRAM exactly once.
// ---------------------------------------------------------------------------
__global__ __launch_bounds__(256) void logits_kernel(
    const float* __restrict__ kb)      // [B, D, S]
{
    const int half = blockIdx.x & 1;
    const int b    = blockIdx.x >> 1;
    const int tid  = threadIdx.x;
    const int wid  = tid >> 5;
    const int lane = tid & 31;
    const int l2   = lane < 17 ? lane : 16;       // clamped second-segment lane
    const float mB = lane < 17 ? 1.f : 0.f;

    __shared__ float w_s[256];
    __shared__ float part[8][200];

    const float* __restrict__ base = kb + (size_t)b * (D * S) + (size_t)half * (256 * S);

    w_s[tid] = g_w[b * D + half * 256 + tid];
    __syncthreads();

    float4 accA = make_float4(0.f, 0.f, 0.f, 0.f);
    float4 accB = make_float4(0.f, 0.f, 0.f, 0.f);

#pragma unroll 4
    for (int r = wid; r < 256; r += 8) {
        const float wv = w_s[r];
        const float4* __restrict__ row = reinterpret_cast<const float4*>(base + r * S);
        float4 va = row[lane];          // s = 4*lane .. +3        (s < 128)
        float4 vb = row[32 + l2];       // s = 128+4*l2 .. +3      (s < 196)
        accA.x += wv * va.x;  accA.y += wv * va.y;
        accA.z += wv * va.z;  accA.w += wv * va.w;
        float wb = wv * mB;
        accB.x += wb * vb.x;  accB.y += wb * vb.y;
        accB.z += wb * vb.z;  accB.w += wb * vb.w;
    }

    // per-warp partials -> smem
    *reinterpret_cast<float4*>(&part[wid][4 * lane]) = accA;
    if (lane < 17)
        *reinterpret_cast<float4*>(&part[wid][128 + 4 * lane]) = accB;
    __syncthreads();

    if (tid < S) {
        float sum = 0.f;
#pragma unroll
        for (int w = 0; w < 8; w++) sum += part[w][tid];
        g_rai[blockIdx.x * 256 + tid] = sum;
    }
}

// ---------------------------------------------------------------------------
// Kernel B: softmax (redundant per CTA, deterministic) + weighted sum.
// Grid 1024 = (b, quarter): each CTA owns 128 e-rows. kb re-read should hit
// L2 (103 MB < 126 MB, just streamed by kernel A).
// ---------------------------------------------------------------------------
__global__ __launch_bounds__(256) void readout_kernel(
    const float* __restrict__ kb,      // [B, D, S]
    float* __restrict__ out)           // [B, D]
{
    const int q    = blockIdx.x & 3;
    const int b    = blockIdx.x >> 2;
    const int tid  = threadIdx.x;
    const int wid  = tid >> 5;
    const int lane = tid & 31;
    const int l2   = lane < 17 ? lane : 16;
    const float mB = lane < 17 ? 1.f : 0.f;

    __shared__ __align__(16) float rvi_s[208];
    __shared__ float red[8];

    // full rai = sum of the two half-partials (fixed order -> deterministic)
    float rai = -INFINITY;
    if (tid < S)
        rai = g_rai[(2 * b) * 256 + tid] + g_rai[(2 * b + 1) * 256 + tid];

    // ---- softmax over s ----
    float m = rai;
#pragma unroll
    for (int off = 16; off > 0; off >>= 1)
        m = fmaxf(m, __shfl_xor_sync(0xffffffff, m, off));
    if (lane == 0) red[wid] = m;
    __syncthreads();
    if (wid == 0) {
        float v = (lane < 8) ? red[lane] : -INFINITY;
#pragma unroll
        for (int off = 4; off > 0; off >>= 1)
            v = fmaxf(v, __shfl_xor_sync(0xffffffff, v, off));
        if (lane == 0) red[0] = v;
    }
    __syncthreads();
    const float gmax = red[0];
    __syncthreads();

    float p = (tid < S) ? expf(rai - gmax) : 0.f;
    float sacc = p;
#pragma unroll
    for (int off = 16; off > 0; off >>= 1)
        sacc += __shfl_xor_sync(0xffffffff, sacc, off);
    if (lane == 0) red[wid] = sacc;
    __syncthreads();
    if (wid == 0) {
        float v = (lane < 8) ? red[lane] : 0.f;
#pragma unroll
        for (int off = 4; off > 0; off >>= 1)
            v += __shfl_xor_sync(0xffffffff, v, off);
        if (lane == 0) red[0] = v;
    }
    __syncthreads();
    const float inv_sum = 1.f / red[0];
    if (tid < S) rvi_s[tid] = p * inv_sum;
    if (tid >= S && tid < 208) rvi_s[tid] = 0.f;
    __syncthreads();

    const float4 rA = *reinterpret_cast<const float4*>(&rvi_s[4 * lane]);
    const float4 rB = *reinterpret_cast<const float4*>(&rvi_s[128 + 4 * l2]);

    const float* __restrict__ base = kb + (size_t)b * (D * S);

    // ---- weighted sum: out[e] = sum_s rvi[s] * kb[e][s], 16 rows per warp ----
#pragma unroll 4
    for (int r = wid; r < 128; r += 8) {
        const int e = q * 128 + r;
        const float4* __restrict__ row = reinterpret_cast<const float4*>(base + e * S);
        float4 va = row[lane];
        float4 vb = row[32 + l2];
        float sum = va.x * rA.x + va.y * rA.y + va.z * rA.z + va.w * rA.w
                  + mB * (vb.x * rB.x + vb.y * rB.y + vb.z * rB.z + vb.w * rB.w);
#pragma unroll
        for (int off = 16; off > 0; off >>= 1)
            sum += __shfl_xor_sync(0xffffffff, sum, off);
        if (lane == 0) out[b * D + e] = sum;
    }
}

extern "C" void kernel_launch(void* const* d_in, const int* in_sizes, int n_in,
                              void* d_out, int out_size)
{
    const float* memory = (const float*)d_in[0];  // [B, D]
    const float* ctrl   = (const float*)d_in[1];  // [B, D]
    const float* kb     = (const float*)d_in[2];  // [B, D, S]
    const float* W      = (const float*)d_in[3];  // [D, D]
    // d_in[4] = b_concat: s-independent shift inside softmax -> drops out
    const float* w_attn = (const float*)d_in[5];  // [D]
    float* out = (float*)d_out;                   // [B, D]

    prep_kernel<<<dim3(4, 32), 1024>>>(memory, ctrl, W, w_attn);
    logits_kernel<<<2 * BATCH, 256>>>(kb);
    readout_kernel<<<4 * BATCH, 256>>>(kb, out);
}